// round 1
// baseline (speedup 1.0000x reference)
#include <cuda_runtime.h>
#include <cstdint>

// Problem constants (max sizes for static scratch)
#define MAX_N 500000
#define FD 5

// Scratch: padded rows of 8 floats (32B = one L2 sector) for aligned vector
// gather + vector RED scatter.
__device__ float g_x[(size_t)MAX_N * 8];     // transformed features (gather src)
__device__ float g_agg[(size_t)MAX_N * 8];   // slots 0-4: sums, slot 5: count (layer 1)
__device__ float g_cntinv[MAX_N];            // 1/max(cnt,1), computed layer 1
__device__ int   g_is64;                     // 1 if edge_index is int64, 0 if int32

// ---------------------------------------------------------------------------
// Vector reduction atomics (sm_90+): one 16B + one 8B RED per edge instead of
// five scalar atomics.
// ---------------------------------------------------------------------------
__device__ __forceinline__ void red4(float* p, float a, float b, float c, float d) {
    asm volatile("red.global.add.v4.f32 [%0], {%1,%2,%3,%4};"
                 :: "l"(p), "f"(a), "f"(b), "f"(c), "f"(d) : "memory");
}
__device__ __forceinline__ void red2(float* p, float a, float b) {
    asm volatile("red.global.add.v2.f32 [%0], {%1,%2};"
                 :: "l"(p), "f"(a), "f"(b) : "memory");
}
__device__ __forceinline__ void red1(float* p, float a) {
    asm volatile("red.global.add.f32 [%0], %1;"
                 :: "l"(p), "f"(a) : "memory");
}

// ---------------------------------------------------------------------------
// Detect whether edge_index is int64 or int32 (jax may silently downcast).
// int32 data reinterpreted as int64 gives values >= 2^32 almost surely.
// ---------------------------------------------------------------------------
__global__ void k_detect(const void* ei, int E, int n) {
    if (blockIdx.x == 0 && threadIdx.x == 0) {
        const long long* p = (const long long*)ei;
        int ok = 1;
        int lim = E < 256 ? E : 256;
        for (int i = 0; i < lim; i++) {
            long long v = p[i];
            if (v < 0 || v >= (long long)n) { ok = 0; break; }
        }
        g_is64 = ok;
    }
}

// ---------------------------------------------------------------------------
// K1: x = h @ W1^T (padded rows), zero agg rows.
// ---------------------------------------------------------------------------
__global__ void __launch_bounds__(256) k_transform_first(
    const float* __restrict__ h, const float* __restrict__ W, int n) {
    int i = blockIdx.x * blockDim.x + threadIdx.x;
    if (i >= n) return;
    float in[FD];
#pragma unroll
    for (int k = 0; k < FD; k++) in[k] = h[(size_t)i * FD + k];
    size_t r = (size_t)i * 8;
#pragma unroll
    for (int f = 0; f < FD; f++) {
        float s = 0.f;
#pragma unroll
        for (int k = 0; k < FD; k++) s += in[k] * __ldg(&W[f * FD + k]);
        g_x[r + f] = s;
    }
    float4 z = make_float4(0.f, 0.f, 0.f, 0.f);
    *(float4*)&g_agg[r] = z;
    *(float4*)&g_agg[r + 4] = z;
}

// ---------------------------------------------------------------------------
// Edge scatter: msg = x[src]*w, RED into agg[dst]. Layer 1 also accumulates
// degree count into slot 5 (packed into the v2 RED for free).
// ---------------------------------------------------------------------------
template <bool FIRST>
__global__ void __launch_bounds__(256) k_edge(
    const void* __restrict__ ei, const float* __restrict__ ew, int E) {
    const bool is64 = (g_is64 != 0);
    int t = blockIdx.x * blockDim.x + threadIdx.x;
    int e0 = t * 2;
    if (e0 >= E) return;
    int cnt2 = (e0 + 1 < E) ? 2 : 1;
#pragma unroll
    for (int j = 0; j < 2; j++) {
        if (j >= cnt2) break;
        int e = e0 + j;
        int s, d;
        if (is64) {
            const long long* p = (const long long*)ei;
            s = (int)__ldg(&p[e]);
            d = (int)__ldg(&p[(size_t)E + e]);
        } else {
            const int* p = (const int*)ei;
            s = __ldg(&p[e]);
            d = __ldg(&p[(size_t)E + e]);
        }
        float w = __ldg(&ew[e]);
        const float4 v = *(const float4*)(g_x + (size_t)s * 8);
        float v4 = g_x[(size_t)s * 8 + 4];
        float* a = g_agg + (size_t)d * 8;
        red4(a, v.x * w, v.y * w, v.z * w, v.w * w);
        if (FIRST) red2(a + 4, v4 * w, 1.0f);
        else       red1(a + 4, v4 * w);
    }
}

// ---------------------------------------------------------------------------
// Finalize layer L + transform for layer L+1: t = relu(agg/cnt + b),
// x = t @ Wnext^T. Re-zeros agg row for the next scatter.
// ---------------------------------------------------------------------------
template <bool FIRST>
__global__ void __launch_bounds__(256) k_finalize_transform(
    const float* __restrict__ b, const float* __restrict__ Wn, int n) {
    int i = blockIdx.x * blockDim.x + threadIdx.x;
    if (i >= n) return;
    size_t r = (size_t)i * 8;
    float4 a0 = *(const float4*)&g_agg[r];
    float a4 = g_agg[r + 4];
    float inv;
    if (FIRST) {
        float c = g_agg[r + 5];
        c = c < 1.f ? 1.f : c;
        inv = 1.f / c;
        g_cntinv[i] = inv;
    } else {
        inv = g_cntinv[i];
    }
    float t[FD] = {a0.x, a0.y, a0.z, a0.w, a4};
#pragma unroll
    for (int k = 0; k < FD; k++) t[k] = fmaxf(t[k] * inv + __ldg(&b[k]), 0.f);
#pragma unroll
    for (int f = 0; f < FD; f++) {
        float s = 0.f;
#pragma unroll
        for (int k = 0; k < FD; k++) s += t[k] * __ldg(&Wn[f * FD + k]);
        g_x[r + f] = s;
    }
    float4 z = make_float4(0.f, 0.f, 0.f, 0.f);
    *(float4*)&g_agg[r] = z;
    *(float4*)&g_agg[r + 4] = z;
}

// ---------------------------------------------------------------------------
// Final: relu(agg/cnt + b3), then fc1(relu) -> fc2(relu) -> fc3, write out.
// ---------------------------------------------------------------------------
__global__ void __launch_bounds__(256) k_final(
    const float* __restrict__ b3,
    const float* __restrict__ fcW1, const float* __restrict__ fcb1,
    const float* __restrict__ fcW2, const float* __restrict__ fcb2,
    const float* __restrict__ fcW3, const float* __restrict__ fcb3,
    float* __restrict__ out, int n) {
    int i = blockIdx.x * blockDim.x + threadIdx.x;
    if (i >= n) return;
    size_t r = (size_t)i * 8;
    float4 a0 = *(const float4*)&g_agg[r];
    float a4 = g_agg[r + 4];
    float inv = g_cntinv[i];
    float t[FD] = {a0.x, a0.y, a0.z, a0.w, a4};
#pragma unroll
    for (int k = 0; k < FD; k++) t[k] = fmaxf(t[k] * inv + __ldg(&b3[k]), 0.f);
    float u1[FD], u2[FD];
#pragma unroll
    for (int f = 0; f < FD; f++) {
        float s = __ldg(&fcb1[f]);
#pragma unroll
        for (int k = 0; k < FD; k++) s += t[k] * __ldg(&fcW1[f * FD + k]);
        u1[f] = fmaxf(s, 0.f);
    }
#pragma unroll
    for (int f = 0; f < FD; f++) {
        float s = __ldg(&fcb2[f]);
#pragma unroll
        for (int k = 0; k < FD; k++) s += u1[k] * __ldg(&fcW2[f * FD + k]);
        u2[f] = fmaxf(s, 0.f);
    }
#pragma unroll
    for (int f = 0; f < FD; f++) {
        float s = __ldg(&fcb3[f]);
#pragma unroll
        for (int k = 0; k < FD; k++) s += u2[k] * __ldg(&fcW3[f * FD + k]);
        out[(size_t)i * FD + f] = s;
    }
}

// ---------------------------------------------------------------------------
extern "C" void kernel_launch(void* const* d_in, const int* in_sizes, int n_in,
                              void* d_out, int out_size) {
    const float* h    = (const float*)d_in[0];
    const void*  ei   = d_in[1];
    const float* ew   = (const float*)d_in[2];
    const float* W1   = (const float*)d_in[3];
    const float* b1   = (const float*)d_in[4];
    const float* W2   = (const float*)d_in[5];
    const float* b2   = (const float*)d_in[6];
    const float* W3   = (const float*)d_in[7];
    const float* b3   = (const float*)d_in[8];
    const float* fcW1 = (const float*)d_in[9];
    const float* fcb1 = (const float*)d_in[10];
    const float* fcW2 = (const float*)d_in[11];
    const float* fcb2 = (const float*)d_in[12];
    const float* fcW3 = (const float*)d_in[13];
    const float* fcb3 = (const float*)d_in[14];
    float* out = (float*)d_out;

    int N = in_sizes[0] / FD;       // 500000
    int E = in_sizes[2];            // 16000000

    int nb = (N + 255) / 256;
    int et = (E + 1) / 2;           // 2 edges per thread
    int eb = (et + 255) / 256;

    k_detect<<<1, 32>>>(ei, E, N);
    k_transform_first<<<nb, 256>>>(h, W1, N);
    k_edge<true><<<eb, 256>>>(ei, ew, E);
    k_finalize_transform<true><<<nb, 256>>>(b1, W2, N);
    k_edge<false><<<eb, 256>>>(ei, ew, E);
    k_finalize_transform<false><<<nb, 256>>>(b2, W3, N);
    k_edge<false><<<eb, 256>>>(ei, ew, E);
    k_final<<<nb, 256>>>(b3, fcW1, fcb1, fcW2, fcb2, fcW3, fcb3, out, N);
}